// round 13
// baseline (speedup 1.0000x reference)
#include <cuda_runtime.h>
#include <cuda_bf16.h>
#include <stdint.h>
#include <math.h>

// ESN: B=64, T=256, I=128, R=2048, O=10, alpha=0.5
#define BB 64
#define TT 256
#define II 128
#define RR 2048
#define OO 10
#define NCTA 256
#define NTHR 256
// 512 gbars/launch x 256 arrivals = 131072 = 2^17 increments per launch

// ---------------- device globals ----------------
__device__ __align__(256) __nv_bfloat16 g_reshi[BB * RR];
__device__ __align__(256) __nv_bfloat16 g_reslo[BB * RR];
__device__ __align__(256) float g_part[16 * 16 * BB * 128];  // [ks][mt][b][jr]
__device__ __align__(128) unsigned g_cnt;

// ---------------- smem layout (bytes), 2-CTA-per-SM budget ----------------
#define ROWB 272  // 256B data + 16 pad -> conflict-free frag LDS
#define SM_A_HI 0
#define SM_A_LO 34816                  // 128*272
#define SM_R_HI 69632                  // 2*128*272
#define SM_R_LO 87040                  // +64*272
#define SM_TOTAL 104448                // +64*272  (x2 CTAs = 209KB < 228KB)

// ---------------- helpers ----------------
static __device__ __forceinline__ unsigned long long dup2(float v) {
    unsigned long long r;
    unsigned u = __float_as_uint(v);
    asm("mov.b64 %0, {%1, %1};" : "=l"(r) : "r"(u));
    return r;
}
static __device__ __forceinline__ void fma2(unsigned long long& a,
                                            unsigned long long x,
                                            unsigned long long y) {
    asm("fma.rn.f32x2 %0, %1, %2, %0;" : "+l"(a) : "l"(x), "l"(y));
}
static __device__ __forceinline__ float lo32(unsigned long long a) {
    return __uint_as_float((unsigned)a);
}
static __device__ __forceinline__ float hi32(unsigned long long a) {
    return __uint_as_float((unsigned)(a >> 32));
}
static __device__ __forceinline__ void mma_bf16(float* d, const unsigned* a,
                                                const unsigned* b) {
    asm volatile(
        "mma.sync.aligned.m16n8k16.row.col.f32.bf16.bf16.f32 "
        "{%0,%1,%2,%3}, {%4,%5,%6,%7}, {%8,%9}, {%0,%1,%2,%3};"
        : "+f"(d[0]), "+f"(d[1]), "+f"(d[2]), "+f"(d[3])
        : "r"(a[0]), "r"(a[1]), "r"(a[2]), "r"(a[3]), "r"(b[0]), "r"(b[1]));
}
static __device__ __forceinline__ void gbar(unsigned target) {
    __syncthreads();
    if (threadIdx.x == 0) {
        asm volatile("red.release.gpu.global.add.u32 [%0], 1;" ::"l"(&g_cnt)
                     : "memory");
        unsigned v;
        int spins = 0;
        for (;;) {
            asm volatile("ld.relaxed.gpu.global.u32 %0, [%1];"
                         : "=r"(v)
                         : "l"(&g_cnt));
            if ((int)(v - target) >= 0) break;
            if (++spins > 2) __nanosleep(40);
        }
        asm volatile("ld.acquire.gpu.global.u32 %0, [%1];"
                     : "=r"(v)
                     : "l"(&g_cnt));
    }
    __syncthreads();
}
static __device__ __forceinline__ unsigned pk(float a, float b) {
    __nv_bfloat162 h = __floats2bfloat162_rn(a, b);
    return *(unsigned*)&h;
}

extern "C" __global__ void __launch_bounds__(NTHR, 2)
esn_mma(const float* __restrict__ x, const float* __restrict__ i2h,
        const float* __restrict__ h2h, const float* __restrict__ ow,
        const float* __restrict__ ob, float* __restrict__ out,
        float* __restrict__ hid) {
    extern __shared__ char sm8[];
    const int tid = threadIdx.x;
    const int cta = blockIdx.x;
    const int mt = cta & 15;  // j block of 128
    const int ks = cta >> 4;  // k block of 128 (16 splits)

    unsigned barBase;
    {
        unsigned v;
        asm volatile("ld.relaxed.gpu.global.u32 %0, [%1];"
                     : "=r"(v)
                     : "l"(&g_cnt));
        barBase = v & ~(unsigned)(512 * NCTA - 1);  // 2^17 per launch
    }
    unsigned barN = 0;

    // ===== Phase 0: transpose own h2h slice into persistent sA (2 passes) ==
    // Consumes A rows j=mt*128..+128, cols k=ks*128..+128.
    {
        float* sT = (float*)(sm8 + SM_R_HI);  // [64][131] fp32 = 33536B
        for (int p = 0; p < 2; p++) {
            __syncthreads();
            for (int idx = tid; idx < 8192; idx += NTHR) {
                int r = idx >> 7, c = idx & 127;
                sT[r * 131 + c] =
                    h2h[(ks * 128 + p * 64 + r) * RR + mt * 128 + c];
            }
            __syncthreads();
            for (int idx = tid; idx < 8192; idx += NTHR) {
                int jl = idx >> 6, kl = idx & 63;
                float v = sT[kl * 131 + jl];  // transpose read (131: cf-free)
                __nv_bfloat16 bhi = __float2bfloat16_rn(v);
                __nv_bfloat16 blo =
                    __float2bfloat16_rn(v - __bfloat162float(bhi));
                uint32_t off = (uint32_t)jl * ROWB + (p * 64 + kl) * 2;
                *(__nv_bfloat16*)(sm8 + SM_A_HI + off) = bhi;
                *(__nv_bfloat16*)(sm8 + SM_A_LO + off) = blo;
            }
        }
        __syncthreads();
    }

    // ===== Phase A: xin = x @ i2h for own 8-col slice (self-consumed) =====
    const int j0c = mt * 128 + ks * 8;
    {
        float* sX = (float*)(sm8 + SM_R_HI);           // [32][132] = 16896B
        float* si = (float*)(sm8 + SM_R_HI + 16896);   // [128][8]  = 4096B
        for (int i = tid; i < II * 8; i += NTHR) {
            int k = i >> 3, jj = i & 7;
            si[i] = i2h[k * RR + j0c + jj];
        }
        const int row = tid >> 2;  // 0..31 for tid<128
        const int j2 = tid & 3;    // float2 group
        for (int rt = 0; rt < BB * TT; rt += 32) {
            __syncthreads();
            for (int i = tid; i < 1024; i += NTHR) {  // 32 rows x 32 float4
                int r = i >> 5, q = i & 31;
                *(float4*)&sX[r * 132 + q * 4] =
                    *(const float4*)&x[(rt + r) * II + q * 4];
            }
            __syncthreads();
            if (tid < 128) {
                unsigned long long a0 = 0ull;
#pragma unroll 8
                for (int k = 0; k < II; k++) {
                    unsigned long long xv = dup2(sX[row * 132 + k]);
                    unsigned long long hv =
                        *(const unsigned long long*)&si[k * 8 + j2 * 2];
                    fma2(a0, xv, hv);
                }
                float2 o = make_float2(lo32(a0), hi32(a0));
                *(float2*)&hid[(rt + row) * RR + j0c + j2 * 2] = o;
            }
        }
        __syncthreads();
    }

    // =========== Scan ===========
    const int w = tid >> 5;
    const int l = tid & 31;
    const int g = l >> 2, tg = l & 3;
    const int mw = w & 3;   // m-pair: jr rows 32mw..32mw+31
    const int nh = w >> 2;  // n-half: b cols 32nh..32nh+31
    // epilogue (tid<128): thread owns (eb = tid>>1, float4 at j0e)
    const int eb = tid >> 1;
    const int ejq = tid & 1;
    const int j0e = j0c + ejq * 4;
    const int jr0 = ks * 8 + ejq * 4;
    float4 p0 = make_float4(0.f, 0.f, 0.f, 0.f);

    const char* sAhi = sm8 + SM_A_HI;
    const char* sAlo = sm8 + SM_A_LO;
    const char* sRhi = sm8 + SM_R_HI;
    const char* sRlo = sm8 + SM_R_LO;
    float* sP = (float*)(sm8 + SM_R_HI);  // [64][132] fp32 partial bounce
    const int pbase = cta * 64;           // (ks*16+mt)*64

    for (int t = 0; t < TT; t++) {
        float4 xv;
        float4 q = make_float4(0.f, 0.f, 0.f, 0.f);
        if (t > 0) {
            // stage res tile [64][128] hi/lo
            for (int idx = tid; idx < 1024; idx += NTHR) {
                int row = idx >> 4, kc = idx & 15;
                *(uint4*)(sm8 + SM_R_HI + row * ROWB + kc * 16) =
                    *(const uint4*)&g_reshi[row * RR + ks * 128 + kc * 8];
                *(uint4*)(sm8 + SM_R_LO + row * ROWB + kc * 16) =
                    *(const uint4*)&g_reslo[row * RR + ks * 128 + kc * 8];
            }
            __syncthreads();
            float acc[2][4][4];
#pragma unroll
            for (int mi = 0; mi < 2; mi++)
#pragma unroll
                for (int ni = 0; ni < 4; ni++)
#pragma unroll
                    for (int qq = 0; qq < 4; qq++) acc[mi][ni][qq] = 0.f;
#pragma unroll
            for (int k16 = 0; k16 < 8; k16++) {
                const int kb = k16 * 32 + 4 * tg;
                unsigned ah[2][4], al[2][4], bh[4][2], bl[4][2];
#pragma unroll
                for (int mi = 0; mi < 2; mi++) {
                    const int rb = (32 * mw + 16 * mi + g) * ROWB;
                    ah[mi][0] = *(const unsigned*)(sAhi + rb + kb);
                    ah[mi][1] = *(const unsigned*)(sAhi + rb + 8 * ROWB + kb);
                    ah[mi][2] = *(const unsigned*)(sAhi + rb + kb + 16);
                    ah[mi][3] =
                        *(const unsigned*)(sAhi + rb + 8 * ROWB + kb + 16);
                    al[mi][0] = *(const unsigned*)(sAlo + rb + kb);
                    al[mi][1] = *(const unsigned*)(sAlo + rb + 8 * ROWB + kb);
                    al[mi][2] = *(const unsigned*)(sAlo + rb + kb + 16);
                    al[mi][3] =
                        *(const unsigned*)(sAlo + rb + 8 * ROWB + kb + 16);
                }
#pragma unroll
                for (int ni = 0; ni < 4; ni++) {
                    const int rb = ((4 * nh + ni) * 8 + g) * ROWB;
                    bh[ni][0] = *(const unsigned*)(sRhi + rb + kb);
                    bh[ni][1] = *(const unsigned*)(sRhi + rb + kb + 16);
                    bl[ni][0] = *(const unsigned*)(sRlo + rb + kb);
                    bl[ni][1] = *(const unsigned*)(sRlo + rb + kb + 16);
                }
#pragma unroll
                for (int mi = 0; mi < 2; mi++)
#pragma unroll
                    for (int ni = 0; ni < 4; ni++)
                        mma_bf16(acc[mi][ni], ah[mi], bh[ni]);
#pragma unroll
                for (int mi = 0; mi < 2; mi++)
#pragma unroll
                    for (int ni = 0; ni < 4; ni++)
                        mma_bf16(acc[mi][ni], ah[mi], bl[ni]);
#pragma unroll
                for (int mi = 0; mi < 2; mi++)
#pragma unroll
                    for (int ni = 0; ni < 4; ni++)
                        mma_bf16(acc[mi][ni], al[mi], bh[ni]);
            }
            __syncthreads();  // res tiles dead; sP overlays R_HI..R_LO
#pragma unroll
            for (int mi = 0; mi < 2; mi++) {
                const int jr = 32 * mw + 16 * mi + g;
#pragma unroll
                for (int ni = 0; ni < 4; ni++) {
                    const int bc = (4 * nh + ni) * 8 + 2 * tg;
                    sP[bc * 132 + jr] = acc[mi][ni][0];
                    sP[(bc + 1) * 132 + jr] = acc[mi][ni][1];
                    sP[bc * 132 + jr + 8] = acc[mi][ni][2];
                    sP[(bc + 1) * 132 + jr + 8] = acc[mi][ni][3];
                }
            }
            __syncthreads();
            for (int i = tid; i < 2048; i += NTHR) {
                const int b = i >> 5, jq = (i & 31) * 4;
                float4 v = *(const float4*)&sP[b * 132 + jq];
                *(float4*)&g_part[(pbase + b) * 128 + jq] = v;
            }
            if (tid < 128) xv = *(const float4*)&hid[(eb * TT + t) * RR + j0e];
            gbar(barBase + NCTA * (++barN));  // sync1: partials ready
            if (tid < 128) {
#pragma unroll
                for (int s = 0; s < 16; s++) {
                    float4 pa = *(const float4*)
                        &g_part[((s * 16 + mt) * 64 + eb) * 128 + jr0];
                    q.x += pa.x; q.y += pa.y; q.z += pa.z; q.w += pa.w;
                }
            }
        } else {
            gbar(barBase + NCTA * (++barN));  // dummy sync1 (uniform count)
            if (tid < 128) xv = *(const float4*)&hid[(eb * TT + t) * RR + j0e];
        }
        // ---- epilogue (tid<128): one float4 (eb, j0e..j0e+3) ----
        if (tid < 128) {
            float4 nr;
            nr.x = 0.5f * p0.x + 0.5f * tanhf(q.x + xv.x);
            nr.y = 0.5f * p0.y + 0.5f * tanhf(q.y + xv.y);
            nr.z = 0.5f * p0.z + 0.5f * tanhf(q.z + xv.z);
            nr.w = 0.5f * p0.w + 0.5f * tanhf(q.w + xv.w);
            p0 = nr;
            *(float4*)&hid[(eb * TT + t) * RR + j0e] = nr;
            float h0 = __bfloat162float(__float2bfloat16_rn(nr.x));
            float h1 = __bfloat162float(__float2bfloat16_rn(nr.y));
            float h2 = __bfloat162float(__float2bfloat16_rn(nr.z));
            float h3 = __bfloat162float(__float2bfloat16_rn(nr.w));
            uint2 uh, ul;
            uh.x = pk(h0, h1);
            uh.y = pk(h2, h3);
            ul.x = pk(nr.x - h0, nr.y - h1);
            ul.y = pk(nr.z - h2, nr.w - h3);
            *(uint2*)&g_reshi[eb * RR + j0e] = uh;
            *(uint2*)&g_reslo[eb * RR + j0e] = ul;
        }
        gbar(barBase + NCTA * (++barN));  // sync2: res ready
    }

    // =========== Readout ===========
    if (cta < BB) {
        const float* res = &hid[(cta * TT + (TT - 1)) * RR];
        float acc[OO];
#pragma unroll
        for (int o = 0; o < OO; o++) acc[o] = 0.f;
        for (int r = tid; r < RR; r += NTHR) {
            float rv = res[r];
#pragma unroll
            for (int o = 0; o < OO; o++) acc[o] += rv * ow[r * OO + o];
        }
        float* red = (float*)sm8;
        __syncthreads();
#pragma unroll
        for (int o = 0; o < OO; o++) red[o * NTHR + tid] = acc[o];
        __syncthreads();
        for (int s2 = NTHR / 2; s2 > 0; s2 >>= 1) {
            if (tid < s2) {
#pragma unroll
                for (int o = 0; o < OO; o++)
                    red[o * NTHR + tid] += red[o * NTHR + tid + s2];
            }
            __syncthreads();
        }
        if (tid < OO) out[cta * OO + tid] = red[tid * NTHR] + ob[tid];
    }
}

extern "C" void kernel_launch(void* const* d_in, const int* in_sizes, int n_in,
                              void* d_out, int out_size) {
    const float* x = (const float*)d_in[0];
    const float* i2h = (const float*)d_in[1];
    const float* h2h = (const float*)d_in[2];
    const float* ow = (const float*)d_in[3];
    const float* ob = (const float*)d_in[4];
    float* out = (float*)d_out;
    float* hid = out + BB * OO;

    cudaFuncSetAttribute(esn_mma, cudaFuncAttributeMaxDynamicSharedMemorySize,
                         SM_TOTAL);
    esn_mma<<<NCTA, NTHR, SM_TOTAL>>>(x, i2h, h2h, ow, ob, out, hid);
}

// round 14
// speedup vs baseline: 1.3793x; 1.3793x over previous
#include <cuda_runtime.h>
#include <cuda_bf16.h>
#include <stdint.h>
#include <math.h>

// ESN: B=64, T=256, I=128, R=2048, O=10, alpha=0.5
#define BB 64
#define TT 256
#define II 128
#define RR 2048
#define OO 10
#define NCTA 128
#define NTHR 256
#define BARS_PER_LAUNCH 512  // 512*128 = 65536 = 2^16 increments per launch

// ---------------- device globals ----------------
__device__ __align__(256) __nv_bfloat16 g_reshi[BB * RR];
__device__ __align__(256) __nv_bfloat16 g_reslo[BB * RR];
__device__ __align__(256) float g_part[8 * 16 * BB * 128];  // [ks][mt][b][jr]
__device__ __align__(128) unsigned g_cnt;

// ---------------- smem layout (bytes) ----------------
#define ROWB 528
#define SM_A_HI 0
#define SM_A_LO (128 * ROWB)            // 67584
#define SM_R_HI (2 * 128 * ROWB)        // 135168 (res hi / sP / x hi)
#define SM_R_LO (SM_R_HI + 64 * ROWB)   // 168960 (res lo / x lo)
#define SM_TOTAL (SM_R_LO + 64 * ROWB)  // 202752

// ---------------- helpers ----------------
static __device__ __forceinline__ uint32_t s2u(const void* p) {
    uint32_t a;
    asm("{ .reg .u64 t; cvta.to.shared.u64 t, %1; cvt.u32.u64 %0, t; }"
        : "=r"(a) : "l"(p));
    return a;
}
static __device__ __forceinline__ void mma_bf16(float* d, const unsigned* a,
                                                const unsigned* b) {
    asm volatile(
        "mma.sync.aligned.m16n8k16.row.col.f32.bf16.bf16.f32 "
        "{%0,%1,%2,%3}, {%4,%5,%6,%7}, {%8,%9}, {%0,%1,%2,%3};"
        : "+f"(d[0]), "+f"(d[1]), "+f"(d[2]), "+f"(d[3])
        : "r"(a[0]), "r"(a[1]), "r"(a[2]), "r"(a[3]), "r"(b[0]), "r"(b[1]));
}
static __device__ __forceinline__ void cpa16(uint32_t dst, const void* src) {
    asm volatile("cp.async.ca.shared.global [%0], [%1], 16;" ::"r"(dst),
                 "l"(src)
                 : "memory");
}
static __device__ __forceinline__ void cpa_commit() {
    asm volatile("cp.async.commit_group;" ::: "memory");
}
template <int N>
static __device__ __forceinline__ void cpa_wait() {
    asm volatile("cp.async.wait_group %0;" ::"n"(N) : "memory");
}
static __device__ __forceinline__ void gbar(unsigned target) {
    __syncthreads();
    if (threadIdx.x == 0) {
        asm volatile("red.release.gpu.global.add.u32 [%0], 1;" ::"l"(&g_cnt)
                     : "memory");
        unsigned v;
        int spins = 0;
        for (;;) {
            asm volatile("ld.relaxed.gpu.global.u32 %0, [%1];"
                         : "=r"(v)
                         : "l"(&g_cnt));
            if ((int)(v - target) >= 0) break;
            if (++spins > 2) __nanosleep(40);
        }
        asm volatile("ld.acquire.gpu.global.u32 %0, [%1];"
                     : "=r"(v)
                     : "l"(&g_cnt));
    }
    __syncthreads();
}
static __device__ __forceinline__ unsigned pk(float a, float b) {
    __nv_bfloat162 h = __floats2bfloat162_rn(a, b);
    return *(unsigned*)&h;
}

extern "C" __global__ void __launch_bounds__(NTHR, 1)
esn_mma(const float* __restrict__ x, const float* __restrict__ i2h,
        const float* __restrict__ h2h, const float* __restrict__ ow,
        const float* __restrict__ ob, float* __restrict__ out,
        float* __restrict__ hid) {
    extern __shared__ char sm8[];
    const uint32_t sb = s2u(sm8);
    const int tid = threadIdx.x;
    const int cta = blockIdx.x;
    const int mt = cta & 15;  // j block of 128
    const int ks = cta >> 4;  // k block of 256

    unsigned barBase;
    {
        unsigned v;
        asm volatile("ld.relaxed.gpu.global.u32 %0, [%1];"
                     : "=r"(v)
                     : "l"(&g_cnt));
        barBase = v & ~(unsigned)(BARS_PER_LAUNCH * NCTA - 1);
    }
    unsigned barN = 0;

    // warp/fragment constants (shared by phase A and scan)
    const int w = tid >> 5;
    const int l = tid & 31;
    const int g = l >> 2, tg = l & 3;
    const int mw = w & 3;   // m-pair: jr rows 32mw..32mw+31
    const int nh = w >> 2;  // n-half: b cols 32nh..32nh+31
    const int tidh = tid - nh * 128;

    const char* sAhi = sm8 + SM_A_HI;
    const char* sAlo = sm8 + SM_A_LO;
    const char* sRhi = sm8 + SM_R_HI;
    const char* sRlo = sm8 + SM_R_LO;
    float* sP = (float*)(sm8 + SM_R_HI);  // [64][132] bounce

    // ===== Phase A0: transpose i2h^T tile (j=mt*128.., k=0..128) into sA ==
    {
        float* sT = (float*)(sm8 + SM_R_HI);  // [64][131] fp32
        for (int p = 0; p < 2; p++) {
            __syncthreads();
            for (int idx = tid; idx < 8192; idx += NTHR) {
                int r = idx >> 7, c = idx & 127;
                sT[r * 131 + c] = i2h[(p * 64 + r) * RR + mt * 128 + c];
            }
            __syncthreads();
            for (int idx = tid; idx < 8192; idx += NTHR) {
                int jl = idx >> 6, kl = idx & 63;
                float v = sT[kl * 131 + jl];
                __nv_bfloat16 bhi = __float2bfloat16_rn(v);
                __nv_bfloat16 blo =
                    __float2bfloat16_rn(v - __bfloat162float(bhi));
                uint32_t off = (uint32_t)jl * ROWB + (p * 64 + kl) * 2;
                *(__nv_bfloat16*)(sm8 + SM_A_HI + off) = bhi;
                *(__nv_bfloat16*)(sm8 + SM_A_LO + off) = blo;
            }
        }
        __syncthreads();
    }

    // ===== Phase A1: xin = x @ i2h via HMMA (32 bt-tiles of 64 per CTA) ===
    for (int it = 0; it < 32; it++) {
        const int nt = it * 8 + ks;
        // stage x[nt*64..+64][0..128] fp32 -> bf16 hi/lo tiles
        for (int idx = tid; idx < 2048; idx += NTHR) {
            int row = idx >> 5, qc = idx & 31;
            float4 v = *(const float4*)&x[(nt * 64 + row) * II + qc * 4];
            float g0 = __bfloat162float(__float2bfloat16_rn(v.x));
            float g1 = __bfloat162float(__float2bfloat16_rn(v.y));
            float g2 = __bfloat162float(__float2bfloat16_rn(v.z));
            float g3 = __bfloat162float(__float2bfloat16_rn(v.w));
            uint2 uh, ul;
            uh.x = pk(v.x, v.y);
            uh.y = pk(v.z, v.w);
            ul.x = pk(v.x - g0, v.y - g1);
            ul.y = pk(v.z - g2, v.w - g3);
            *(uint2*)(sm8 + SM_R_HI + row * ROWB + qc * 8) = uh;
            *(uint2*)(sm8 + SM_R_LO + row * ROWB + qc * 8) = ul;
        }
        __syncthreads();
        float acc[2][4][4];
#pragma unroll
        for (int mi = 0; mi < 2; mi++)
#pragma unroll
            for (int ni = 0; ni < 4; ni++)
#pragma unroll
                for (int qq = 0; qq < 4; qq++) acc[mi][ni][qq] = 0.f;
#pragma unroll
        for (int k16 = 0; k16 < 8; k16++) {
            const int kb = k16 * 32 + 4 * tg;
            unsigned ah[2][4], al[2][4], bh[4][2], bl[4][2];
#pragma unroll
            for (int mi = 0; mi < 2; mi++) {
                const int rb = (32 * mw + 16 * mi + g) * ROWB;
                ah[mi][0] = *(const unsigned*)(sAhi + rb + kb);
                ah[mi][1] = *(const unsigned*)(sAhi + rb + 8 * ROWB + kb);
                ah[mi][2] = *(const unsigned*)(sAhi + rb + kb + 16);
                ah[mi][3] = *(const unsigned*)(sAhi + rb + 8 * ROWB + kb + 16);
                al[mi][0] = *(const unsigned*)(sAlo + rb + kb);
                al[mi][1] = *(const unsigned*)(sAlo + rb + 8 * ROWB + kb);
                al[mi][2] = *(const unsigned*)(sAlo + rb + kb + 16);
                al[mi][3] = *(const unsigned*)(sAlo + rb + 8 * ROWB + kb + 16);
            }
#pragma unroll
            for (int ni = 0; ni < 4; ni++) {
                const int rb = ((4 * nh + ni) * 8 + g) * ROWB;
                bh[ni][0] = *(const unsigned*)(sRhi + rb + kb);
                bh[ni][1] = *(const unsigned*)(sRhi + rb + kb + 16);
                bl[ni][0] = *(const unsigned*)(sRlo + rb + kb);
                bl[ni][1] = *(const unsigned*)(sRlo + rb + kb + 16);
            }
#pragma unroll
            for (int mi = 0; mi < 2; mi++)
#pragma unroll
                for (int ni = 0; ni < 4; ni++)
                    mma_bf16(acc[mi][ni], ah[mi], bh[ni]);
#pragma unroll
            for (int mi = 0; mi < 2; mi++)
#pragma unroll
                for (int ni = 0; ni < 4; ni++)
                    mma_bf16(acc[mi][ni], ah[mi], bl[ni]);
#pragma unroll
            for (int mi = 0; mi < 2; mi++)
#pragma unroll
                for (int ni = 0; ni < 4; ni++)
                    mma_bf16(acc[mi][ni], al[mi], bh[ni]);
        }
        __syncthreads();  // x tiles dead; sP overlays
#pragma unroll
        for (int mi = 0; mi < 2; mi++) {
            const int jr = 32 * mw + 16 * mi + g;
#pragma unroll
            for (int ni = 0; ni < 4; ni++) {
                const int bc = (4 * nh + ni) * 8 + 2 * tg;
                sP[bc * 132 + jr] = acc[mi][ni][0];
                sP[(bc + 1) * 132 + jr] = acc[mi][ni][1];
                sP[bc * 132 + jr + 8] = acc[mi][ni][2];
                sP[(bc + 1) * 132 + jr + 8] = acc[mi][ni][3];
            }
        }
        __syncthreads();
        for (int i = tid; i < 2048; i += NTHR) {
            const int b = i >> 5, jq = (i & 31) * 4;
            float4 v = *(const float4*)&sP[b * 132 + jq];
            *(float4*)&hid[(nt * 64 + b) * RR + mt * 128 + jq] = v;
        }
        __syncthreads();
    }
    gbar(barBase + NCTA * (++barN));

    // ===== Phase 0: transpose own h2h slice into persistent sA ============
    {
        float* sT = (float*)(sm8 + SM_R_HI);  // [128][131] fp32 (67072B)
        for (int rep = 0; rep < 2; rep++) {
            int ti = 2 * ks + rep;
            __syncthreads();
            for (int idx = tid; idx < 16384; idx += NTHR) {
                int r = idx >> 7, c = idx & 127;
                sT[r * 131 + c] = h2h[(ti * 128 + r) * RR + mt * 128 + c];
            }
            __syncthreads();
            for (int idx = tid; idx < 16384; idx += NTHR) {
                int jl = idx >> 7, kl = idx & 127;
                float v = sT[kl * 131 + jl];
                __nv_bfloat16 bhi = __float2bfloat16_rn(v);
                __nv_bfloat16 blo =
                    __float2bfloat16_rn(v - __bfloat162float(bhi));
                uint32_t off = (uint32_t)jl * ROWB + (rep * 128 + kl) * 2;
                *(__nv_bfloat16*)(sm8 + SM_A_HI + off) = bhi;
                *(__nv_bfloat16*)(sm8 + SM_A_LO + off) = blo;
            }
        }
        __syncthreads();
    }

    // =========== Scan ===========
    const int gt = cta * NTHR + tid;
    const int b_e = gt >> 9;
    const int j0 = (gt & 511) * 4;
    const int mt_e = j0 >> 7, jr0 = j0 & 127;
    float4 p0 = make_float4(0.f, 0.f, 0.f, 0.f);
    float4 pend;
    const int pbase = (ks * 16 + mt) * 64;

    auto issue_chunk = [&](int c) {
#pragma unroll
        for (int jj = 0; jj < 2; jj++) {
            int p = tid + 256 * jj;  // 0..511
            int row = p >> 3, kc = c * 8 + (p & 7);
            uint32_t so = (uint32_t)(row * ROWB + kc * 16);
            cpa16(sb + SM_R_HI + so, &g_reshi[row * RR + ks * 256 + kc * 8]);
            cpa16(sb + SM_R_LO + so, &g_reslo[row * RR + ks * 256 + kc * 8]);
        }
        cpa_commit();
    };

    for (int t = 0; t < TT; t++) {
        float4 xv;
        float4 q = make_float4(0.f, 0.f, 0.f, 0.f);
        if (t > 0) {
            issue_chunk(0);
            issue_chunk(1);
            *(float4*)&hid[(b_e * TT + (t - 1)) * RR + j0] = pend;
            float acc[2][4][4];
#pragma unroll
            for (int mi = 0; mi < 2; mi++)
#pragma unroll
                for (int ni = 0; ni < 4; ni++)
#pragma unroll
                    for (int qq = 0; qq < 4; qq++) acc[mi][ni][qq] = 0.f;
#pragma unroll
            for (int c = 0; c < 4; c++) {
                if (c == 3) cpa_wait<0>();
                else cpa_wait<1>();
                __syncthreads();
                if (c < 2) issue_chunk(c + 2);
#pragma unroll
                for (int kk = 0; kk < 4; kk++) {
                    const int kb = (c * 4 + kk) * 32 + 4 * tg;
                    unsigned ah[2][4], al[2][4], bh[4][2], bl[4][2];
#pragma unroll
                    for (int mi = 0; mi < 2; mi++) {
                        const int rb = (32 * mw + 16 * mi + g) * ROWB;
                        ah[mi][0] = *(const unsigned*)(sAhi + rb + kb);
                        ah[mi][1] =
                            *(const unsigned*)(sAhi + rb + 8 * ROWB + kb);
                        ah[mi][2] = *(const unsigned*)(sAhi + rb + kb + 16);
                        ah[mi][3] =
                            *(const unsigned*)(sAhi + rb + 8 * ROWB + kb + 16);
                        al[mi][0] = *(const unsigned*)(sAlo + rb + kb);
                        al[mi][1] =
                            *(const unsigned*)(sAlo + rb + 8 * ROWB + kb);
                        al[mi][2] = *(const unsigned*)(sAlo + rb + kb + 16);
                        al[mi][3] =
                            *(const unsigned*)(sAlo + rb + 8 * ROWB + kb + 16);
                    }
#pragma unroll
                    for (int ni = 0; ni < 4; ni++) {
                        const int rb = ((4 * nh + ni) * 8 + g) * ROWB;
                        bh[ni][0] = *(const unsigned*)(sRhi + rb + kb);
                        bh[ni][1] = *(const unsigned*)(sRhi + rb + kb + 16);
                        bl[ni][0] = *(const unsigned*)(sRlo + rb + kb);
                        bl[ni][1] = *(const unsigned*)(sRlo + rb + kb + 16);
                    }
#pragma unroll
                    for (int mi = 0; mi < 2; mi++)
#pragma unroll
                        for (int ni = 0; ni < 4; ni++)
                            mma_bf16(acc[mi][ni], ah[mi], bh[ni]);
#pragma unroll
                    for (int mi = 0; mi < 2; mi++)
#pragma unroll
                        for (int ni = 0; ni < 4; ni++)
                            mma_bf16(acc[mi][ni], ah[mi], bl[ni]);
#pragma unroll
                    for (int mi = 0; mi < 2; mi++)
#pragma unroll
                        for (int ni = 0; ni < 4; ni++)
                            mma_bf16(acc[mi][ni], al[mi], bh[ni]);
                }
            }
            // per-half join (sP rows overlay the half's own res rows)
            {
                const int bid = 1 + nh;
                asm volatile("bar.sync %0, %1;" ::"r"(bid), "r"(128)
                             : "memory");
#pragma unroll
                for (int mi = 0; mi < 2; mi++) {
                    const int jr = 32 * mw + 16 * mi + g;
#pragma unroll
                    for (int ni = 0; ni < 4; ni++) {
                        const int bc = (4 * nh + ni) * 8 + 2 * tg;
                        sP[bc * 132 + jr] = acc[mi][ni][0];
                        sP[(bc + 1) * 132 + jr] = acc[mi][ni][1];
                        sP[bc * 132 + jr + 8] = acc[mi][ni][2];
                        sP[(bc + 1) * 132 + jr + 8] = acc[mi][ni][3];
                    }
                }
                asm volatile("bar.sync %0, %1;" ::"r"(bid), "r"(128)
                             : "memory");
                for (int i = tidh; i < 1024; i += 128) {
                    const int b = nh * 32 + (i >> 5), jq = (i & 31) * 4;
                    float4 v = *(const float4*)&sP[b * 132 + jq];
                    *(float4*)&g_part[(pbase + b) * 128 + jq] = v;
                }
            }
            xv = *(const float4*)&hid[(b_e * TT + t) * RR + j0];
            gbar(barBase + NCTA * (++barN));  // sync1: partials ready
#pragma unroll
            for (int s = 0; s < 8; s++) {
                float4 pa = *(const float4*)
                    &g_part[((s * 16 + mt_e) * 64 + b_e) * 128 + jr0];
                q.x += pa.x; q.y += pa.y; q.z += pa.z; q.w += pa.w;
            }
        } else {
            xv = *(const float4*)&hid[(b_e * TT + t) * RR + j0];
        }
        // ---- epilogue ----
        float4 nr;
        nr.x = 0.5f * p0.x + 0.5f * tanhf(q.x + xv.x);
        nr.y = 0.5f * p0.y + 0.5f * tanhf(q.y + xv.y);
        nr.z = 0.5f * p0.z + 0.5f * tanhf(q.z + xv.z);
        nr.w = 0.5f * p0.w + 0.5f * tanhf(q.w + xv.w);
        p0 = nr;
        if (t == TT - 1) {
            *(float4*)&hid[(b_e * TT + t) * RR + j0] = nr;
        } else {
            pend = nr;
        }
        float h0 = __bfloat162float(__float2bfloat16_rn(nr.x));
        float h1 = __bfloat162float(__float2bfloat16_rn(nr.y));
        float h2 = __bfloat162float(__float2bfloat16_rn(nr.z));
        float h3 = __bfloat162float(__float2bfloat16_rn(nr.w));
        uint2 uh, ul;
        uh.x = pk(h0, h1);
        uh.y = pk(h2, h3);
        ul.x = pk(nr.x - h0, nr.y - h1);
        ul.y = pk(nr.z - h2, nr.w - h3);
        *(uint2*)&g_reshi[b_e * RR + j0] = uh;
        *(uint2*)&g_reslo[b_e * RR + j0] = ul;
        gbar(barBase + NCTA * (++barN));  // sync2: res ready
    }

    // =========== Readout ===========
    if (cta < BB) {
        const float* res = &hid[(cta * TT + (TT - 1)) * RR];
        float acc[OO];
#pragma unroll
        for (int o = 0; o < OO; o++) acc[o] = 0.f;
        for (int r = tid; r < RR; r += NTHR) {
            float rv = res[r];
#pragma unroll
            for (int o = 0; o < OO; o++) acc[o] += rv * ow[r * OO + o];
        }
        float* red = (float*)sm8;
        __syncthreads();
#pragma unroll
        for (int o = 0; o < OO; o++) red[o * NTHR + tid] = acc[o];
        __syncthreads();
        for (int s2 = NTHR / 2; s2 > 0; s2 >>= 1) {
            if (tid < s2) {
#pragma unroll
                for (int o = 0; o < OO; o++)
                    red[o * NTHR + tid] += red[o * NTHR + tid + s2];
            }
            __syncthreads();
        }
        if (tid < OO) out[cta * OO + tid] = red[tid * NTHR] + ob[tid];
    }
}

extern "C" void kernel_launch(void* const* d_in, const int* in_sizes, int n_in,
                              void* d_out, int out_size) {
    const float* x = (const float*)d_in[0];
    const float* i2h = (const float*)d_in[1];
    const float* h2h = (const float*)d_in[2];
    const float* ow = (const float*)d_in[3];
    const float* ob = (const float*)d_in[4];
    float* out = (float*)d_out;
    float* hid = out + BB * OO;

    cudaFuncSetAttribute(esn_mma, cudaFuncAttributeMaxDynamicSharedMemorySize,
                         SM_TOTAL);
    esn_mma<<<NCTA, NTHR, SM_TOTAL>>>(x, i2h, h2h, ow, ob, out, hid);
}

// round 15
// speedup vs baseline: 1.9003x; 1.3777x over previous
#include <cuda_runtime.h>
#include <cuda_bf16.h>
#include <stdint.h>
#include <math.h>

// ESN: B=64, T=256, I=128, R=2048, O=10, alpha=0.5
#define BB 64
#define TT 256
#define II 128
#define RR 2048
#define OO 10
#define NCTA 128
#define NTHR 256
#define BARS_PER_LAUNCH 512  // 512*128 = 65536 = 2^16 increments per launch

// ---------------- device globals ----------------
__device__ __align__(256) __nv_bfloat16 g_reshi[BB * RR];
__device__ __align__(256) __nv_bfloat16 g_reslo[BB * RR];
__device__ __align__(256) float g_part[8 * 16 * BB * 128];  // [ks][mt][b][jr]
__device__ __align__(128) unsigned g_cnt;

// ---------------- smem layout (bytes) ----------------
#define ROWB 528
#define SM_A_HI 0
#define SM_A_LO (128 * ROWB)            // 67584
#define SM_R_HI (2 * 128 * ROWB)        // 135168 (res hi / sP / x hi)
#define SM_R_LO (SM_R_HI + 64 * ROWB)   // 168960 (res lo / x lo)
#define SM_TOTAL (SM_R_LO + 64 * ROWB)  // 202752

// ---------------- helpers ----------------
static __device__ __forceinline__ void mma_bf16(float* d, const unsigned* a,
                                                const unsigned* b) {
    asm volatile(
        "mma.sync.aligned.m16n8k16.row.col.f32.bf16.bf16.f32 "
        "{%0,%1,%2,%3}, {%4,%5,%6,%7}, {%8,%9}, {%0,%1,%2,%3};"
        : "+f"(d[0]), "+f"(d[1]), "+f"(d[2]), "+f"(d[3])
        : "r"(a[0]), "r"(a[1]), "r"(a[2]), "r"(a[3]), "r"(b[0]), "r"(b[1]));
}
static __device__ __forceinline__ void gbar(unsigned target) {
    __syncthreads();
    if (threadIdx.x == 0) {
        asm volatile("red.release.gpu.global.add.u32 [%0], 1;" ::"l"(&g_cnt)
                     : "memory");
        unsigned v;
        int spins = 0;
        for (;;) {
            asm volatile("ld.relaxed.gpu.global.u32 %0, [%1];"
                         : "=r"(v)
                         : "l"(&g_cnt));
            if ((int)(v - target) >= 0) break;
            if (++spins > 2) __nanosleep(40);
        }
        asm volatile("ld.acquire.gpu.global.u32 %0, [%1];"
                     : "=r"(v)
                     : "l"(&g_cnt));
    }
    __syncthreads();
}
static __device__ __forceinline__ unsigned pk(float a, float b) {
    __nv_bfloat162 h = __floats2bfloat162_rn(a, b);
    return *(unsigned*)&h;
}

extern "C" __global__ void __launch_bounds__(NTHR, 1)
esn_mma(const float* __restrict__ x, const float* __restrict__ i2h,
        const float* __restrict__ h2h, const float* __restrict__ ow,
        const float* __restrict__ ob, float* __restrict__ out,
        float* __restrict__ hid) {
    extern __shared__ char sm8[];
    const int tid = threadIdx.x;
    const int cta = blockIdx.x;
    const int mt = cta & 15;  // j block of 128
    const int ks = cta >> 4;  // k block of 256

    unsigned barBase;
    {
        unsigned v;
        asm volatile("ld.relaxed.gpu.global.u32 %0, [%1];"
                     : "=r"(v)
                     : "l"(&g_cnt));
        barBase = v & ~(unsigned)(BARS_PER_LAUNCH * NCTA - 1);
    }
    unsigned barN = 0;

    // warp/fragment constants (shared by phase A and scan)
    const int w = tid >> 5;
    const int l = tid & 31;
    const int g = l >> 2, tg = l & 3;
    const int mw = w & 3;   // m-pair: jr rows 32mw..32mw+31
    const int nh = w >> 2;  // n-half: b cols 32nh..32nh+31
    const int tidh = tid - nh * 128;

    const char* sAhi = sm8 + SM_A_HI;
    const char* sAlo = sm8 + SM_A_LO;
    const char* sRhi = sm8 + SM_R_HI;
    const char* sRlo = sm8 + SM_R_LO;
    float* sP = (float*)(sm8 + SM_R_HI);  // [64][132] bounce

    // ===== Phase A0: transpose i2h^T tile (j=mt*128.., k=0..128) into sA ==
    {
        float* sT = (float*)(sm8 + SM_R_HI);  // [64][131] fp32
        for (int p = 0; p < 2; p++) {
            __syncthreads();
            for (int idx = tid; idx < 8192; idx += NTHR) {
                int r = idx >> 7, c = idx & 127;
                sT[r * 131 + c] = i2h[(p * 64 + r) * RR + mt * 128 + c];
            }
            __syncthreads();
            for (int idx = tid; idx < 8192; idx += NTHR) {
                int jl = idx >> 6, kl = idx & 63;
                float v = sT[kl * 131 + jl];
                __nv_bfloat16 bhi = __float2bfloat16_rn(v);
                __nv_bfloat16 blo =
                    __float2bfloat16_rn(v - __bfloat162float(bhi));
                uint32_t off = (uint32_t)jl * ROWB + (p * 64 + kl) * 2;
                *(__nv_bfloat16*)(sm8 + SM_A_HI + off) = bhi;
                *(__nv_bfloat16*)(sm8 + SM_A_LO + off) = blo;
            }
        }
        __syncthreads();
    }

    // ===== Phase A1: xin = x @ i2h via HMMA (32 bt-tiles of 64 per CTA) ===
    for (int it = 0; it < 32; it++) {
        const int nt = it * 8 + ks;
        // stage x[nt*64..+64][0..128] fp32 -> bf16 hi/lo tiles
        for (int idx = tid; idx < 2048; idx += NTHR) {
            int row = idx >> 5, qc = idx & 31;
            float4 v = *(const float4*)&x[(nt * 64 + row) * II + qc * 4];
            float g0 = __bfloat162float(__float2bfloat16_rn(v.x));
            float g1 = __bfloat162float(__float2bfloat16_rn(v.y));
            float g2 = __bfloat162float(__float2bfloat16_rn(v.z));
            float g3 = __bfloat162float(__float2bfloat16_rn(v.w));
            uint2 uh, ul;
            uh.x = pk(v.x, v.y);
            uh.y = pk(v.z, v.w);
            ul.x = pk(v.x - g0, v.y - g1);
            ul.y = pk(v.z - g2, v.w - g3);
            *(uint2*)(sm8 + SM_R_HI + row * ROWB + qc * 8) = uh;
            *(uint2*)(sm8 + SM_R_LO + row * ROWB + qc * 8) = ul;
        }
        __syncthreads();
        float acc[2][4][4];
#pragma unroll
        for (int mi = 0; mi < 2; mi++)
#pragma unroll
            for (int ni = 0; ni < 4; ni++)
#pragma unroll
                for (int qq = 0; qq < 4; qq++) acc[mi][ni][qq] = 0.f;
#pragma unroll
        for (int k16 = 0; k16 < 8; k16++) {
            const int kb = k16 * 32 + 4 * tg;
            unsigned ah[2][4], al[2][4], bh[4][2], bl[4][2];
#pragma unroll
            for (int mi = 0; mi < 2; mi++) {
                const int rb = (32 * mw + 16 * mi + g) * ROWB;
                ah[mi][0] = *(const unsigned*)(sAhi + rb + kb);
                ah[mi][1] = *(const unsigned*)(sAhi + rb + 8 * ROWB + kb);
                ah[mi][2] = *(const unsigned*)(sAhi + rb + kb + 16);
                ah[mi][3] = *(const unsigned*)(sAhi + rb + 8 * ROWB + kb + 16);
                al[mi][0] = *(const unsigned*)(sAlo + rb + kb);
                al[mi][1] = *(const unsigned*)(sAlo + rb + 8 * ROWB + kb);
                al[mi][2] = *(const unsigned*)(sAlo + rb + kb + 16);
                al[mi][3] = *(const unsigned*)(sAlo + rb + 8 * ROWB + kb + 16);
            }
#pragma unroll
            for (int ni = 0; ni < 4; ni++) {
                const int rb = ((4 * nh + ni) * 8 + g) * ROWB;
                bh[ni][0] = *(const unsigned*)(sRhi + rb + kb);
                bh[ni][1] = *(const unsigned*)(sRhi + rb + kb + 16);
                bl[ni][0] = *(const unsigned*)(sRlo + rb + kb);
                bl[ni][1] = *(const unsigned*)(sRlo + rb + kb + 16);
            }
#pragma unroll
            for (int mi = 0; mi < 2; mi++)
#pragma unroll
                for (int ni = 0; ni < 4; ni++)
                    mma_bf16(acc[mi][ni], ah[mi], bh[ni]);
#pragma unroll
            for (int mi = 0; mi < 2; mi++)
#pragma unroll
                for (int ni = 0; ni < 4; ni++)
                    mma_bf16(acc[mi][ni], ah[mi], bl[ni]);
#pragma unroll
            for (int mi = 0; mi < 2; mi++)
#pragma unroll
                for (int ni = 0; ni < 4; ni++)
                    mma_bf16(acc[mi][ni], al[mi], bh[ni]);
        }
        __syncthreads();  // x tiles dead; sP overlays
#pragma unroll
        for (int mi = 0; mi < 2; mi++) {
            const int jr = 32 * mw + 16 * mi + g;
#pragma unroll
            for (int ni = 0; ni < 4; ni++) {
                const int bc = (4 * nh + ni) * 8 + 2 * tg;
                sP[bc * 132 + jr] = acc[mi][ni][0];
                sP[(bc + 1) * 132 + jr] = acc[mi][ni][1];
                sP[bc * 132 + jr + 8] = acc[mi][ni][2];
                sP[(bc + 1) * 132 + jr + 8] = acc[mi][ni][3];
            }
        }
        __syncthreads();
        for (int i = tid; i < 2048; i += NTHR) {
            const int b = i >> 5, jq = (i & 31) * 4;
            float4 v = *(const float4*)&sP[b * 132 + jq];
            *(float4*)&hid[(nt * 64 + b) * RR + mt * 128 + jq] = v;
        }
        __syncthreads();
    }
    gbar(barBase + NCTA * (++barN));

    // ===== Phase 0: transpose own h2h slice into persistent sA ============
    {
        float* sT = (float*)(sm8 + SM_R_HI);  // [128][131] fp32 (67072B)
        for (int rep = 0; rep < 2; rep++) {
            int ti = 2 * ks + rep;
            __syncthreads();
            for (int idx = tid; idx < 16384; idx += NTHR) {
                int r = idx >> 7, c = idx & 127;
                sT[r * 131 + c] = h2h[(ti * 128 + r) * RR + mt * 128 + c];
            }
            __syncthreads();
            for (int idx = tid; idx < 16384; idx += NTHR) {
                int jl = idx >> 7, kl = idx & 127;
                float v = sT[kl * 131 + jl];
                __nv_bfloat16 bhi = __float2bfloat16_rn(v);
                __nv_bfloat16 blo =
                    __float2bfloat16_rn(v - __bfloat162float(bhi));
                uint32_t off = (uint32_t)jl * ROWB + (rep * 128 + kl) * 2;
                *(__nv_bfloat16*)(sm8 + SM_A_HI + off) = bhi;
                *(__nv_bfloat16*)(sm8 + SM_A_LO + off) = blo;
            }
        }
        __syncthreads();
    }

    // =========== Scan (R10 champion body) ===========
    const int gt = cta * NTHR + tid;
    const int b_e = gt >> 9;
    const int j0 = (gt & 511) * 4;
    const int mt_e = j0 >> 7, jr0 = j0 & 127;
    float4 p0 = make_float4(0.f, 0.f, 0.f, 0.f);
    float4 pend;
    const int pbase = (ks * 16 + mt) * 64;

    for (int t = 0; t < TT; t++) {
        float4 xv;
        float4 q = make_float4(0.f, 0.f, 0.f, 0.f);
        if (t > 0) {
            // stage res tile [64][256] hi/lo (plain uint4 loads)
            for (int idx = tid; idx < 2048; idx += NTHR) {
                int row = idx >> 5, kc = idx & 31;
                *(uint4*)(sm8 + SM_R_HI + row * ROWB + kc * 16) =
                    *(const uint4*)&g_reshi[row * RR + ks * 256 + kc * 8];
                *(uint4*)(sm8 + SM_R_LO + row * ROWB + kc * 16) =
                    *(const uint4*)&g_reslo[row * RR + ks * 256 + kc * 8];
            }
            *(float4*)&hid[(b_e * TT + (t - 1)) * RR + j0] = pend;
            __syncthreads();
            float acc[2][4][4];
#pragma unroll
            for (int mi = 0; mi < 2; mi++)
#pragma unroll
                for (int ni = 0; ni < 4; ni++)
#pragma unroll
                    for (int qq = 0; qq < 4; qq++) acc[mi][ni][qq] = 0.f;
#pragma unroll 2
            for (int k16 = 0; k16 < 16; k16++) {
                const int kb = k16 * 32 + 4 * tg;
                unsigned ah[2][4], al[2][4], bh[4][2], bl[4][2];
#pragma unroll
                for (int mi = 0; mi < 2; mi++) {
                    const int rb = (32 * mw + 16 * mi + g) * ROWB;
                    ah[mi][0] = *(const unsigned*)(sAhi + rb + kb);
                    ah[mi][1] = *(const unsigned*)(sAhi + rb + 8 * ROWB + kb);
                    ah[mi][2] = *(const unsigned*)(sAhi + rb + kb + 16);
                    ah[mi][3] =
                        *(const unsigned*)(sAhi + rb + 8 * ROWB + kb + 16);
                    al[mi][0] = *(const unsigned*)(sAlo + rb + kb);
                    al[mi][1] = *(const unsigned*)(sAlo + rb + 8 * ROWB + kb);
                    al[mi][2] = *(const unsigned*)(sAlo + rb + kb + 16);
                    al[mi][3] =
                        *(const unsigned*)(sAlo + rb + 8 * ROWB + kb + 16);
                }
#pragma unroll
                for (int ni = 0; ni < 4; ni++) {
                    const int rb = ((4 * nh + ni) * 8 + g) * ROWB;
                    bh[ni][0] = *(const unsigned*)(sRhi + rb + kb);
                    bh[ni][1] = *(const unsigned*)(sRhi + rb + kb + 16);
                    bl[ni][0] = *(const unsigned*)(sRlo + rb + kb);
                    bl[ni][1] = *(const unsigned*)(sRlo + rb + kb + 16);
                }
#pragma unroll
                for (int mi = 0; mi < 2; mi++)
#pragma unroll
                    for (int ni = 0; ni < 4; ni++)
                        mma_bf16(acc[mi][ni], ah[mi], bh[ni]);
#pragma unroll
                for (int mi = 0; mi < 2; mi++)
#pragma unroll
                    for (int ni = 0; ni < 4; ni++)
                        mma_bf16(acc[mi][ni], ah[mi], bl[ni]);
#pragma unroll
                for (int mi = 0; mi < 2; mi++)
#pragma unroll
                    for (int ni = 0; ni < 4; ni++)
                        mma_bf16(acc[mi][ni], al[mi], bh[ni]);
            }
            // per-half join (disjoint sP rows overlay the half's own res rows)
            {
                const int bid = 1 + nh;
                asm volatile("bar.sync %0, %1;" ::"r"(bid), "r"(128)
                             : "memory");
#pragma unroll
                for (int mi = 0; mi < 2; mi++) {
                    const int jr = 32 * mw + 16 * mi + g;
#pragma unroll
                    for (int ni = 0; ni < 4; ni++) {
                        const int bc = (4 * nh + ni) * 8 + 2 * tg;
                        sP[bc * 132 + jr] = acc[mi][ni][0];
                        sP[(bc + 1) * 132 + jr] = acc[mi][ni][1];
                        sP[bc * 132 + jr + 8] = acc[mi][ni][2];
                        sP[(bc + 1) * 132 + jr + 8] = acc[mi][ni][3];
                    }
                }
                asm volatile("bar.sync %0, %1;" ::"r"(bid), "r"(128)
                             : "memory");
                for (int i = tidh; i < 1024; i += 128) {
                    const int b = nh * 32 + (i >> 5), jq = (i & 31) * 4;
                    float4 v = *(const float4*)&sP[b * 132 + jq];
                    *(float4*)&g_part[(pbase + b) * 128 + jq] = v;
                }
            }
            xv = *(const float4*)&hid[(b_e * TT + t) * RR + j0];
            gbar(barBase + NCTA * (++barN));  // sync1: partials ready
#pragma unroll
            for (int s = 0; s < 8; s++) {
                float4 pa = *(const float4*)
                    &g_part[((s * 16 + mt_e) * 64 + b_e) * 128 + jr0];
                q.x += pa.x; q.y += pa.y; q.z += pa.z; q.w += pa.w;
            }
        } else {
            xv = *(const float4*)&hid[(b_e * TT + t) * RR + j0];
        }
        // ---- epilogue ----
        float4 nr;
        nr.x = 0.5f * p0.x + 0.5f * tanhf(q.x + xv.x);
        nr.y = 0.5f * p0.y + 0.5f * tanhf(q.y + xv.y);
        nr.z = 0.5f * p0.z + 0.5f * tanhf(q.z + xv.z);
        nr.w = 0.5f * p0.w + 0.5f * tanhf(q.w + xv.w);
        p0 = nr;
        if (t == TT - 1) {
            *(float4*)&hid[(b_e * TT + t) * RR + j0] = nr;
        } else {
            pend = nr;
        }
        float h0 = __bfloat162float(__float2bfloat16_rn(nr.x));
        float h1 = __bfloat162float(__float2bfloat16_rn(nr.y));
        float h2 = __bfloat162float(__float2bfloat16_rn(nr.z));
        float h3 = __bfloat162float(__float2bfloat16_rn(nr.w));
        uint2 uh, ul;
        uh.x = pk(h0, h1);
        uh.y = pk(h2, h3);
        ul.x = pk(nr.x - h0, nr.y - h1);
        ul.y = pk(nr.z - h2, nr.w - h3);
        *(uint2*)&g_reshi[b_e * RR + j0] = uh;
        *(uint2*)&g_reslo[b_e * RR + j0] = ul;
        gbar(barBase + NCTA * (++barN));  // sync2: res ready
    }

    // =========== Readout ===========
    if (cta < BB) {
        const float* res = &hid[(cta * TT + (TT - 1)) * RR];
        float acc[OO];
#pragma unroll
        for (int o = 0; o < OO; o++) acc[o] = 0.f;
        for (int r = tid; r < RR; r += NTHR) {
            float rv = res[r];
#pragma unroll
            for (int o = 0; o < OO; o++) acc[o] += rv * ow[r * OO + o];
        }
        float* red = (float*)sm8;
        __syncthreads();
#pragma unroll
        for (int o = 0; o < OO; o++) red[o * NTHR + tid] = acc[o];
        __syncthreads();
        for (int s2 = NTHR / 2; s2 > 0; s2 >>= 1) {
            if (tid < s2) {
#pragma unroll
                for (int o = 0; o < OO; o++)
                    red[o * NTHR + tid] += red[o * NTHR + tid + s2];
            }
            __syncthreads();
        }
        if (tid < OO) out[cta * OO + tid] = red[tid * NTHR] + ob[tid];
    }
}

extern "C" void kernel_launch(void* const* d_in, const int* in_sizes, int n_in,
                              void* d_out, int out_size) {
    const float* x = (const float*)d_in[0];
    const float* i2h = (const float*)d_in[1];
    const float* h2h = (const float*)d_in[2];
    const float* ow = (const float*)d_in[3];
    const float* ob = (const float*)d_in[4];
    float* out = (float*)d_out;
    float* hid = out + BB * OO;

    cudaFuncSetAttribute(esn_mma, cudaFuncAttributeMaxDynamicSharedMemorySize,
                         SM_TOTAL);
    esn_mma<<<NCTA, NTHR, SM_TOTAL>>>(x, i2h, h2h, ow, ob, out, hid);
}